// round 3
// baseline (speedup 1.0000x reference)
#include <cuda_runtime.h>
#include <math.h>

#define BSZ 4
#define CH  128
#define HH  128
#define WW  128
#define HWP (HH*WW)

typedef unsigned long long u64;

// -------- packed f32x2 helpers (SASS FFMA2) --------
__device__ __forceinline__ void ffma2(u64 &d, u64 a, u64 b){
    asm("fma.rn.f32x2 %0, %1, %2, %0;" : "+l"(d) : "l"(a), "l"(b));
}
__device__ __forceinline__ u64 pack2(float x, float y){
    u64 r; asm("mov.b64 %0, {%1, %2};" : "=l"(r) : "f"(x), "f"(y)); return r;
}
__device__ __forceinline__ void unpack2(u64 p, float &lo, float &hi){
    asm("mov.b64 {%0, %1}, %2;" : "=f"(lo), "=f"(hi) : "l"(p));
}

// -------- scratch (static device memory; no allocations) --------
__device__ float g_r1 [(size_t)BSZ*CH*HWP];   // bn1 output
__device__ float g_d1 [(size_t)BSZ*CH*HWP];   // layer1 output (post-prelu)
__device__ float g_offm[(size_t)BSZ*27*HWP];  // ch 0..17 offsets, 18..26 mask
__device__ float g_wT1[9*CH*CH];              // w1 transposed [k][c][co]
__device__ float g_wT2[9*CH*CH];              // w2 transposed [k][c][co]

// -------- prep: transpose main conv weights to [k][c][co] --------
__global__ void prep_wt_kernel(const float* __restrict__ w1, const float* __restrict__ w2){
    int i = blockIdx.x*256 + threadIdx.x;
    const int N = 9*CH*CH;
    if (i >= 2*N) return;
    const float* w = (i < N) ? w1 : w2;
    float*       o = (i < N) ? g_wT1 : g_wT2;
    int j = (i < N) ? i : i - N;
    int co = j & (CH-1);
    int c  = (j >> 7) & (CH-1);
    int k  = j >> 14;
    o[j] = w[(co*CH + c)*9 + k];
}

// -------- bn1 elementwise --------
__global__ void bn1_kernel(const float4* __restrict__ x,
                           const float* __restrict__ g, const float* __restrict__ b,
                           const float* __restrict__ m, const float* __restrict__ v){
    int i = blockIdx.x*256 + threadIdx.x;          // over BSZ*CH*HWP/4 float4s
    int c = (i >> 12) & (CH-1);
    float s  = g[c] * rsqrtf(v[c] + 1e-5f);
    float bb = b[c] - m[c]*s;
    float4 xv = x[i];
    float4 r;
    r.x = xv.x*s + bb; r.y = xv.y*s + bb; r.z = xv.z*s + bb; r.w = xv.w*s + bb;
    ((float4*)g_r1)[i] = r;
}

// -------- fused offset(18) + mask(9) 3x3 conv, pad 1, co split in halves --------
// grid: 256 blocks = BSZ * (HH/4) * 2 halves.  block: 256 thr, 2 px/thread.
// half 0 -> co 0..13 (14 outputs), half 1 -> co 14..26 (13 outputs)
__global__ void __launch_bounds__(256,2)
offmod_kernel(const float* __restrict__ src,
              const float* __restrict__ offw, const float* __restrict__ offb,
              const float* __restrict__ modw, const float* __restrict__ modb){
    extern __shared__ float sm[];
    float* wsm   = sm;              // [c*9+k][16] (co pairs, padded) -> 1152*16 floats
    float* patch = sm + 1152*16;    // 6 x 130 floats

    int t    = threadIdx.x;
    int half = blockIdx.x & 1;
    int h0   = ((blockIdx.x >> 1) & 31) * 4;
    int b    = blockIdx.x >> 6;

    int coBase = half * 14;
    int nCo    = half ? 13 : 14;

    // stage this half's weights into smem: wsm[r*16 + j] = w[coBase+j][r], zero pad
    for (int i = t; i < 1152*16; i += 256){
        int r = i >> 4;
        int j = i & 15;
        int cg = coBase + j;
        float val = 0.f;
        if (j < nCo)
            val = (cg < 18) ? offw[cg*1152 + r] : modw[(cg-18)*1152 + r];
        wsm[i] = val;
    }

    int p0 = 2*t;
    int tr = p0 >> 7;               // tile row 0..3
    int tw = p0 & 127;              // even col

    u64 acc2[8][2];                 // [co pair 0..7][px 0..1]
#pragma unroll
    for (int p = 0; p < 8; p++){ acc2[p][0] = 0ull; acc2[p][1] = 0ull; }

    for (int c = 0; c < CH; c++){
        __syncthreads();
        const float* sp = src + ((size_t)(b*CH + c))*HWP;
        for (int i = t; i < 780; i += 256){
            int pr = i / 130; int pc = i - pr*130;
            int y  = h0 - 1 + pr;
            int xx = pc - 1;
            float vv = 0.f;
            if ((unsigned)y < HH && (unsigned)xx < WW) vv = sp[y*WW + xx];
            patch[i] = vv;
        }
        __syncthreads();
#pragma unroll
        for (int k = 0; k < 9; k++){
            int ky = k/3, kx = k - ky*3;
            float v0 = patch[(tr+ky)*130 + tw + kx];
            float v1 = patch[(tr+ky)*130 + tw + kx + 1];
            u64 v0d = pack2(v0, v0);
            u64 v1d = pack2(v1, v1);
            const ulonglong2* wr = (const ulonglong2*)(wsm + (c*9 + k)*16);
#pragma unroll
            for (int q = 0; q < 4; q++){
                ulonglong2 wq = wr[q];
                ffma2(acc2[2*q  ][0], wq.x, v0d);
                ffma2(acc2[2*q  ][1], wq.x, v1d);
                ffma2(acc2[2*q+1][0], wq.y, v0d);
                ffma2(acc2[2*q+1][1], wq.y, v1d);
            }
        }
    }

    int h = h0 + tr;
    size_t pbase = (size_t)h*WW + tw;
#pragma unroll
    for (int p = 0; p < 8; p++){
        float a0lo, a0hi, a1lo, a1hi;
        unpack2(acc2[p][0], a0lo, a0hi);
        unpack2(acc2[p][1], a1lo, a1hi);
#pragma unroll
        for (int e = 0; e < 2; e++){
            int j  = 2*p + e;
            if (j >= nCo) continue;
            int co = coBase + j;
            float a0 = e ? a0hi : a0lo;
            float a1 = e ? a1hi : a1lo;
            if (co < 18){
                float bb = offb[co];
                a0 += bb; a1 += bb;
            } else {
                float bb = modb[co-18];
                a0 = 2.f/(1.f + __expf(-(a0 + bb)));
                a1 = 2.f/(1.f + __expf(-(a1 + bb)));
            }
            float* op = g_offm + ((size_t)(b*27 + co))*HWP + pbase;
            *(float2*)op = make_float2(a0, a1);
        }
    }
}

// -------- deformable conv implicit GEMM (FFMA2 core) --------
// grid: 1024 blocks = BSZ*HH*2 ; block 256 thr; tile = 64 px (one h-row half)
// MODE 0: out = prelu(conv) -> g_d1  (p0 = alpha)
// MODE 1: out = bn2(conv) + x -> d_out (p0 = x, bn params used)
template<int MODE>
__global__ void __launch_bounds__(256,3)
deform_kernel(const float* __restrict__ src, const float* __restrict__ wT,
              const float* __restrict__ p0,
              const float* __restrict__ bn_g, const float* __restrict__ bn_b,
              const float* __restrict__ bn_m, const float* __restrict__ bn_v,
              float* __restrict__ out){
    extern __shared__ float dynsm[];
    float* cols2 = dynsm;                     // [c][2*px] duplicated pairs: CH*128 floats (64KB)
    float* s_wt  = dynsm + CH*128;            // 64*4
    int*   s_ad  = (int*)(dynsm + CH*128 + 256);

    int t   = threadIdx.x;
    int b   = blockIdx.x >> 8;
    int rem = blockIdx.x & 255;
    int h   = rem >> 1;
    int w0  = (rem & 1) << 6;

    int tx  = t & 15;
    int ty  = t >> 4;
    int ty2 = ty*2;
    int pxme = t & 63;

    u64 acc2[4][4];                 // [co pair][px]
#pragma unroll
    for (int j = 0; j < 4; j++)
#pragma unroll
        for (int i = 0; i < 4; i++) acc2[j][i] = 0ull;

    const float* srcb  = src + (size_t)b*CH*HWP;
    const float* offb_ = g_offm + (size_t)b*27*HWP;

    for (int k = 0; k < 9; k++){
        __syncthreads();
        if (t < 64){
            int w = w0 + t;
            int p = h*WW + w;
            float oy = offb_[(2*k  )*HWP + p];
            float ox = offb_[(2*k+1)*HWP + p];
            float mv = offb_[(18+k )*HWP + p];
            int ky = k/3, kx = k - ky*3;
            float py  = (float)(h - 1 + ky) + oy;
            float pxf = (float)(w - 1 + kx) + ox;
            float y0f = floorf(py), x0f = floorf(pxf);
            float ay = py - y0f, ax = pxf - x0f;
            int y0 = (int)y0f, x0 = (int)x0f;
#pragma unroll
            for (int j = 0; j < 4; j++){
                int dy = j >> 1, dx = j & 1;
                int yi = y0 + dy, xi = x0 + dx;
                bool ok = ((unsigned)yi < HH) && ((unsigned)xi < WW);
                int yc = min(max(yi, 0), HH-1);
                int xc = min(max(xi, 0), WW-1);
                float wy = dy ? ay : 1.f - ay;
                float wx = dx ? ax : 1.f - ax;
                s_ad[t*4+j] = yc*WW + xc;
                s_wt[t*4+j] = ok ? wy*wx*mv : 0.f;
            }
        }
        __syncthreads();

        // sample cols for this k; store value duplicated as an f32x2 pair
        int a0 = s_ad[pxme*4+0], a1 = s_ad[pxme*4+1], a2 = s_ad[pxme*4+2], a3 = s_ad[pxme*4+3];
        float f0 = s_wt[pxme*4+0], f1 = s_wt[pxme*4+1], f2 = s_wt[pxme*4+2], f3 = s_wt[pxme*4+3];
        int cstart = t >> 6;
#pragma unroll 8
        for (int s = 0; s < 32; s++){
            int c = cstart + s*4;
            const float* sp = srcb + (size_t)c*HWP;
            float v = f0*sp[a0] + f1*sp[a1] + f2*sp[a2] + f3*sp[a3];
            ((u64*)cols2)[c*64 + pxme] = pack2(v, v);
        }
        __syncthreads();

        // FFMA2 fragment: acc2[cp][px] += (w_co,w_co+1) * (v_px,v_px)
        const ulonglong2* cc = (const ulonglong2*)cols2;
        const ulonglong2* wp = (const ulonglong2*)(wT + (size_t)k*CH*CH);
#pragma unroll 4
        for (int c = 0; c < CH; c++){
            ulonglong2 cva = cc[c*32 + tx*2];      // px0, px1 (each duplicated)
            ulonglong2 cvb = cc[c*32 + tx*2 + 1];  // px2, px3
            ulonglong2 w01 = wp[c*32 + ty2];       // co pairs 0,1
            ulonglong2 w23 = wp[c*32 + ty2 + 1];   // co pairs 2,3
            ffma2(acc2[0][0], w01.x, cva.x);
            ffma2(acc2[0][1], w01.x, cva.y);
            ffma2(acc2[0][2], w01.x, cvb.x);
            ffma2(acc2[0][3], w01.x, cvb.y);
            ffma2(acc2[1][0], w01.y, cva.x);
            ffma2(acc2[1][1], w01.y, cva.y);
            ffma2(acc2[1][2], w01.y, cvb.x);
            ffma2(acc2[1][3], w01.y, cvb.y);
            ffma2(acc2[2][0], w23.x, cva.x);
            ffma2(acc2[2][1], w23.x, cva.y);
            ffma2(acc2[2][2], w23.x, cvb.x);
            ffma2(acc2[2][3], w23.x, cvb.y);
            ffma2(acc2[3][0], w23.y, cva.x);
            ffma2(acc2[3][1], w23.y, cva.y);
            ffma2(acc2[3][2], w23.y, cvb.x);
            ffma2(acc2[3][3], w23.y, cvb.y);
        }
    }

    // epilogue: unpack co pairs
    int co0  = ty*8;
    int wcol = w0 + tx*4;
    size_t obase = ((size_t)b*CH)*HWP + (size_t)h*WW + wcol;
#pragma unroll
    for (int cp = 0; cp < 4; cp++){
        float lo[4], hi[4];
#pragma unroll
        for (int i = 0; i < 4; i++) unpack2(acc2[cp][i], lo[i], hi[i]);
        int coA = co0 + 2*cp;
        int coB = coA + 1;
        if (MODE == 0){
            float aA = p0[coA], aB = p0[coB];
            float4 oA, oB;
            oA.x = lo[0] > 0.f ? lo[0] : aA*lo[0];
            oA.y = lo[1] > 0.f ? lo[1] : aA*lo[1];
            oA.z = lo[2] > 0.f ? lo[2] : aA*lo[2];
            oA.w = lo[3] > 0.f ? lo[3] : aA*lo[3];
            oB.x = hi[0] > 0.f ? hi[0] : aB*hi[0];
            oB.y = hi[1] > 0.f ? hi[1] : aB*hi[1];
            oB.z = hi[2] > 0.f ? hi[2] : aB*hi[2];
            oB.w = hi[3] > 0.f ? hi[3] : aB*hi[3];
            *(float4*)(out + obase + (size_t)coA*HWP) = oA;
            *(float4*)(out + obase + (size_t)coB*HWP) = oB;
        } else {
            float sA  = bn_g[coA] * rsqrtf(bn_v[coA] + 1e-5f);
            float bA  = bn_b[coA] - bn_m[coA]*sA;
            float sB  = bn_g[coB] * rsqrtf(bn_v[coB] + 1e-5f);
            float bB  = bn_b[coB] - bn_m[coB]*sB;
            float4 xA = *(const float4*)(p0 + obase + (size_t)coA*HWP);
            float4 xB = *(const float4*)(p0 + obase + (size_t)coB*HWP);
            float4 oA, oB;
            oA.x = lo[0]*sA + bA + xA.x;
            oA.y = lo[1]*sA + bA + xA.y;
            oA.z = lo[2]*sA + bA + xA.z;
            oA.w = lo[3]*sA + bA + xA.w;
            oB.x = hi[0]*sB + bB + xB.x;
            oB.y = hi[1]*sB + bB + xB.y;
            oB.z = hi[2]*sB + bB + xB.z;
            oB.w = hi[3]*sB + bB + xB.w;
            *(float4*)(out + obase + (size_t)coA*HWP) = oA;
            *(float4*)(out + obase + (size_t)coB*HWP) = oB;
        }
    }
}

// -------- host launcher --------
extern "C" void kernel_launch(void* const* d_in, const int* in_sizes, int n_in,
                              void* d_out, int out_size){
    const float* x      = (const float*)d_in[0];
    const float* bn1_g  = (const float*)d_in[1];
    const float* bn1_b  = (const float*)d_in[2];
    const float* bn1_m  = (const float*)d_in[3];
    const float* bn1_v  = (const float*)d_in[4];
    const float* off1_w = (const float*)d_in[5];
    const float* off1_b = (const float*)d_in[6];
    const float* mod1_w = (const float*)d_in[7];
    const float* mod1_b = (const float*)d_in[8];
    const float* w1     = (const float*)d_in[9];
    const float* alpha  = (const float*)d_in[10];
    const float* off2_w = (const float*)d_in[11];
    const float* off2_b = (const float*)d_in[12];
    const float* mod2_w = (const float*)d_in[13];
    const float* mod2_b = (const float*)d_in[14];
    const float* w2     = (const float*)d_in[15];
    const float* bn2_g  = (const float*)d_in[16];
    const float* bn2_b  = (const float*)d_in[17];
    const float* bn2_m  = (const float*)d_in[18];
    const float* bn2_v  = (const float*)d_in[19];
    float* out = (float*)d_out;

    float *r1p, *d1p, *wt1p, *wt2p;
    cudaGetSymbolAddress((void**)&r1p,  g_r1);
    cudaGetSymbolAddress((void**)&d1p,  g_d1);
    cudaGetSymbolAddress((void**)&wt1p, g_wT1);
    cudaGetSymbolAddress((void**)&wt2p, g_wT2);

    const int OFFMOD_SMEM = (1152*16 + 780) * (int)sizeof(float);   // ~77 KB
    const int DEFORM_SMEM = (CH*128 + 256 + 256) * (int)sizeof(float); // 66 KB
    cudaFuncSetAttribute(offmod_kernel, cudaFuncAttributeMaxDynamicSharedMemorySize, OFFMOD_SMEM);
    cudaFuncSetAttribute(deform_kernel<0>, cudaFuncAttributeMaxDynamicSharedMemorySize, DEFORM_SMEM);
    cudaFuncSetAttribute(deform_kernel<1>, cudaFuncAttributeMaxDynamicSharedMemorySize, DEFORM_SMEM);

    // 1) weight transposes
    prep_wt_kernel<<<(2*9*CH*CH + 255)/256, 256>>>(w1, w2);
    // 2) bn1
    bn1_kernel<<<(BSZ*CH*HWP/4)/256, 256>>>((const float4*)x, bn1_g, bn1_b, bn1_m, bn1_v);
    // 3) offsets + mask for layer 1
    offmod_kernel<<<256, 256, OFFMOD_SMEM>>>(r1p, off1_w, off1_b, mod1_w, mod1_b);
    // 4) deform conv 1 (+prelu) -> d1
    deform_kernel<0><<<1024, 256, DEFORM_SMEM>>>(r1p, wt1p, alpha, nullptr, nullptr, nullptr, nullptr, d1p);
    // 5) offsets + mask for layer 2
    offmod_kernel<<<256, 256, OFFMOD_SMEM>>>(d1p, off2_w, off2_b, mod2_w, mod2_b);
    // 6) deform conv 2 (+bn2 +shortcut) -> out
    deform_kernel<1><<<1024, 256, DEFORM_SMEM>>>(d1p, wt2p, x, bn2_g, bn2_b, bn2_m, bn2_v, out);
}